// round 1
// baseline (speedup 1.0000x reference)
#include <cuda_runtime.h>

// ---------------------------------------------------------------------------
// GraphSAGE fused pipeline, fp32 SIMT baseline.
//
// Shapes: B=1024, F=256, D=256, OUT=128, EXP=[10,25]
//   h0 (B,1,256) h1 (B,10,256) h2 (B,250,256)
//   mask0 (B,10) mask1 (B,250)
//   W_self0/W_neigh0/W_pool0 (256,256)
//   W_self1/W_neigh1 (256,512), W_pool1 (256,256), W_out (128,512)
// ---------------------------------------------------------------------------

#define KC 32           // K chunk (floats) per smem stage
#define NPOOL 256       // pool kernel output columns (always 256)

// Scratch (static device globals — no allocation allowed)
__device__ float g_pool1 [10240 * 256];   // masked-max-pooled neighbors, layer0 j=1
__device__ float g_pool0 [1024  * 256];   // layer0 j=0
__device__ float g_state1[10240 * 512];   // states[1] after layer0
__device__ float g_state0[1024  * 512];   // states[0] after layer0
__device__ float g_pooled[1024  * 256];   // layer1 pooled
__device__ float g_fin   [1024  * 512];   // states[0] after layer1

// ---------------------------------------------------------------------------
// pool_kernel<S>: Y[g,n] = max_{s<S} relu( dot(X[g*S+s, :K], W[n, :K]) ) * mask[g*S+s]
// One CTA per group g. 128 threads; thread t owns columns t and t+128.
// All candidates are >= 0, so max-accumulator init 0 is exact.
// ---------------------------------------------------------------------------
template <int S>
__global__ __launch_bounds__(128) void pool_kernel(
    const float* __restrict__ X,     // (G*S, K) row-major
    const float* __restrict__ W,     // (256, K) row-major
    const float* __restrict__ mask,  // (G*S)
    float* __restrict__ Y,           // (G, 256)
    int K)
{
    __shared__ float4 Wv[KC / 4][NPOOL];   // Wv[j][n] = W[n][k0+4j .. k0+4j+3]
    __shared__ float4 Xs[S][KC / 4];
    __shared__ float  msk[S];

    const int g = blockIdx.x;
    const int t = threadIdx.x;
    const float* Xg = X + (size_t)g * S * K;

    if (t < S) msk[t] = mask[(size_t)g * S + t];

    float acc0[S], acc1[S];
#pragma unroll
    for (int s = 0; s < S; s++) { acc0[s] = 0.f; acc1[s] = 0.f; }

    for (int k0 = 0; k0 < K; k0 += KC) {
        // stage X chunk: S rows x 8 float4
#pragma unroll
        for (int idx = t; idx < S * (KC / 4); idx += 128) {
            int row = idx / (KC / 4), j = idx % (KC / 4);
            Xs[row][j] =
                *reinterpret_cast<const float4*>(&Xg[(size_t)row * K + k0 + 4 * j]);
        }
        // stage W chunk: 256 rows x 8 float4 = 2048, 16 per thread
#pragma unroll
        for (int i = 0; i < 16; i++) {
            int idx = t + i * 128;
            int n = idx >> 3, j = idx & 7;
            Wv[j][n] =
                *reinterpret_cast<const float4*>(&W[(size_t)n * K + k0 + 4 * j]);
        }
        __syncthreads();

#pragma unroll
        for (int j = 0; j < KC / 4; j++) {
            float4 w0 = Wv[j][t];
            float4 w1 = Wv[j][t + 128];
#pragma unroll
            for (int s = 0; s < S; s++) {
                float4 x = Xs[s][j];
                acc0[s] += x.x * w0.x + x.y * w0.y + x.z * w0.z + x.w * w0.w;
                acc1[s] += x.x * w1.x + x.y * w1.y + x.z * w1.z + x.w * w1.w;
            }
        }
        __syncthreads();
    }

    float m0 = 0.f, m1 = 0.f;
#pragma unroll
    for (int s = 0; s < S; s++) {
        float mm = msk[s];
        m0 = fmaxf(m0, fmaxf(acc0[s], 0.f) * mm);
        m1 = fmaxf(m1, fmaxf(acc1[s], 0.f) * mm);
    }
    Y[(size_t)g * NPOOL + t]       = m0;
    Y[(size_t)g * NPOOL + t + 128] = m1;
}

// ---------------------------------------------------------------------------
// gemm_kernel: Y[m, n] = dot(X[m,:K], W[n,:K]) for a 16-row block, N<=256 cols.
// Output written at Y + m*ldy + n (ldy lets us write concat halves in place).
// M must be a multiple of 16; N in {128, 256}.
// ---------------------------------------------------------------------------
__global__ __launch_bounds__(128) void gemm_kernel(
    const float* __restrict__ X, int K,
    const float* __restrict__ W, int N,
    float* __restrict__ Y, int ldy)
{
    __shared__ float4 Wv[KC / 4][256];
    __shared__ float4 Xs[16][KC / 4];

    const int row0 = blockIdx.x * 16;
    const int t = threadIdx.x;

    float acc0[16], acc1[16];
#pragma unroll
    for (int r = 0; r < 16; r++) { acc0[r] = 0.f; acc1[r] = 0.f; }

    const int nload = N * (KC / 4);  // float4 count for W chunk

    for (int k0 = 0; k0 < K; k0 += KC) {
        {
            int row = t >> 3, j = t & 7;
            Xs[row][j] = *reinterpret_cast<const float4*>(
                &X[(size_t)(row0 + row) * K + k0 + 4 * j]);
        }
        for (int idx = t; idx < nload; idx += 128) {
            int n = idx >> 3, j = idx & 7;
            Wv[j][n] =
                *reinterpret_cast<const float4*>(&W[(size_t)n * K + k0 + 4 * j]);
        }
        __syncthreads();

#pragma unroll
        for (int j = 0; j < KC / 4; j++) {
            float4 w0 = Wv[j][t];
            float4 w1 = (t + 128 < N) ? Wv[j][t + 128] : make_float4(0.f, 0.f, 0.f, 0.f);
#pragma unroll
            for (int r = 0; r < 16; r++) {
                float4 x = Xs[r][j];
                acc0[r] += x.x * w0.x + x.y * w0.y + x.z * w0.z + x.w * w0.w;
                acc1[r] += x.x * w1.x + x.y * w1.y + x.z * w1.z + x.w * w1.w;
            }
        }
        __syncthreads();
    }

#pragma unroll
    for (int r = 0; r < 16; r++) {
        Y[(size_t)(row0 + r) * ldy + t] = acc0[r];
        if (t + 128 < N)
            Y[(size_t)(row0 + r) * ldy + t + 128] = acc1[r];
    }
}

// ---------------------------------------------------------------------------
// Host driver: 10 graph-capturable launches on the default stream.
// ---------------------------------------------------------------------------
extern "C" void kernel_launch(void* const* d_in, const int* in_sizes, int n_in,
                              void* d_out, int out_size)
{
    const float* h0    = (const float*)d_in[0];
    const float* h1    = (const float*)d_in[1];
    const float* h2    = (const float*)d_in[2];
    const float* mask0 = (const float*)d_in[3];
    const float* mask1 = (const float*)d_in[4];
    const float* Ws0   = (const float*)d_in[5];
    const float* Wn0   = (const float*)d_in[6];
    const float* Wp0   = (const float*)d_in[7];
    const float* Ws1   = (const float*)d_in[8];
    const float* Wn1   = (const float*)d_in[9];
    const float* Wp1   = (const float*)d_in[10];
    const float* Wout  = (const float*)d_in[11];
    float* out = (float*)d_out;

    float *pool1, *pool0, *state1, *state0, *pooled, *fin;
    cudaGetSymbolAddress((void**)&pool1,  g_pool1);
    cudaGetSymbolAddress((void**)&pool0,  g_pool0);
    cudaGetSymbolAddress((void**)&state1, g_state1);
    cudaGetSymbolAddress((void**)&state0, g_state0);
    cudaGetSymbolAddress((void**)&pooled, g_pooled);
    cudaGetSymbolAddress((void**)&fin,    g_fin);

    const int B = 1024;

    // ---- layer 0 ----
    // j=1: neighbors h2 (B*10 groups of 25), W_neigh0, mask1 -> pool1 (B*10,256)
    pool_kernel<25><<<B * 10, 128>>>(h2, Wn0, mask1, pool1, 256);
    // j=0: neighbors h1 (B groups of 10), W_neigh0, mask0 -> pool0 (B,256)
    pool_kernel<10><<<B, 128>>>(h1, Wn0, mask0, pool0, 256);

    // state1 = concat( h1 @ Ws0^T , pool1 @ Wp0^T )  -> (B*10, 512)
    gemm_kernel<<<(B * 10) / 16, 128>>>(h1,    256, Ws0, 256, state1,       512);
    gemm_kernel<<<(B * 10) / 16, 128>>>(pool1, 256, Wp0, 256, state1 + 256, 512);

    // state0 = concat( h0 @ Ws0^T , pool0 @ Wp0^T )  -> (B, 512)
    gemm_kernel<<<B / 16, 128>>>(h0,    256, Ws0, 256, state0,       512);
    gemm_kernel<<<B / 16, 128>>>(pool0, 256, Wp0, 256, state0 + 256, 512);

    // ---- layer 1 (j=0) ----
    // pooled = maxpool_s relu(state1 @ Wn1^T) * mask0  -> (B, 256)
    pool_kernel<10><<<B, 128>>>(state1, Wn1, mask0, pooled, 512);

    // fin = concat( state0 @ Ws1^T , pooled @ Wp1^T )  -> (B, 512)
    gemm_kernel<<<B / 16, 128>>>(state0, 512, Ws1, 256, fin,       512);
    gemm_kernel<<<B / 16, 128>>>(pooled, 256, Wp1, 256, fin + 256, 512);

    // ---- output ----
    // out = fin @ Wout^T  -> (B, 128)
    gemm_kernel<<<B / 16, 128>>>(fin, 512, Wout, 128, out, 128);
}

// round 3
// speedup vs baseline: 4.6167x; 4.6167x over previous
#include <cuda_runtime.h>
#include <cstdint>

// ---------------------------------------------------------------------------
// GraphSAGE via mma.sync tf32 tensor cores (portable PTX path; tcgen05 is
// rejected by this toolchain's plain-sm_103 ptxas target).
// Shapes: B=1024, F=D=256, OUT=128, EXP=[10,25]
// ---------------------------------------------------------------------------

#define THREADS 256
#define LDA 36                     // smem row stride in floats (conflict-free frags)
#define STAGE_BYTES (128 * LDA * 4)
#define EPI_STRIDE 132
#define SMEM_DYN (512 + 128 * EPI_STRIDE * 4)   // 512B mask | max(stage, epi buf)

// Scratch (static device globals — no allocation allowed)
__device__ float g_pool1 [10240 * 256];
__device__ float g_pool0 [1024  * 256];
__device__ float g_state1[10240 * 512];
__device__ float g_state0[1024  * 512];
__device__ float g_pooled[1024  * 256];
__device__ float g_fin   [1024  * 512];

__device__ __forceinline__ float tf32_rn(float x) {   // round-to-nearest -> tf32
    uint32_t r;
    asm("cvt.rna.tf32.f32 %0, %1;" : "=r"(r) : "f"(x));
    return __uint_as_float(r);
}

__device__ __forceinline__ void mma8(float* c, const uint32_t* a, const uint32_t* b) {
    asm volatile(
        "mma.sync.aligned.m16n8k8.row.col.f32.tf32.tf32.f32 "
        "{%0,%1,%2,%3}, {%4,%5,%6,%7}, {%8,%9}, {%0,%1,%2,%3};"
        : "+f"(c[0]), "+f"(c[1]), "+f"(c[2]), "+f"(c[3])
        : "r"(a[0]), "r"(a[1]), "r"(a[2]), "r"(a[3]), "r"(b[0]), "r"(b[1]));
}

// ---------------------------------------------------------------------------
// mma_kernel<S>: Y = X @ W^T on tensor cores. CTA tile 128(M) x 128(N).
//   grid.x tiles M (RPC rows per CTA), grid.y tiles N in 128-col halves.
//   S == 0 : plain GEMM, Y[row*ldy + bIdx.y*128 + n].
//   S > 0  : fused masked-relu-max pool over groups of S rows;
//            Y[group*256 + bIdx.y*128 + n]. Padded rows get mask=0 (exact,
//            all pooled candidates are >= 0).
// X (Mtot, K) row-major; W (gridDim.y*128, K) row-major.
// ---------------------------------------------------------------------------
template <int S>
__global__ __launch_bounds__(THREADS) void mma_kernel(
    const float* __restrict__ X, const float* __restrict__ W,
    const float* __restrict__ mask, float* __restrict__ Y,
    int K, int Mtot, int ldy)
{
    constexpr int RPC = (S == 25) ? 125 : (S == 10) ? 120 : 128;
    constexpr int GPC = S ? RPC / S : 0;

    extern __shared__ char smem[];
    float* msk = (float*)smem;                 // [128]
    float* As  = (float*)(smem + 512);         // [128][LDA]
    float* Bs  = (float*)(smem + 512 + STAGE_BYTES);
    float* buf = (float*)(smem + 512);         // epilogue reuse [128][EPI_STRIDE]

    const int t    = threadIdx.x;
    const int lane = t & 31;
    const int warp = t >> 5;
    const int wm   = warp >> 1;                // 0..3 (M)
    const int wn   = warp & 1;                 // 0..1 (N)
    const int tr   = lane >> 2;                // 0..7
    const int tc   = lane & 3;                 // 0..3

    const int row0 = blockIdx.x * RPC;
    const float* Wb = W + (size_t)blockIdx.y * 128 * K;

    if (S && t < 128) {
        int rg = row0 + t;
        msk[t] = (t < RPC && rg < Mtot) ? mask[rg] : 0.f;
    }

    const int ldrow = t >> 3, ldc4 = t & 7;    // staging map: 8 float4 per row

    float4 pa[4], pb[4];
    auto prefetch = [&](int k0) {
#pragma unroll
        for (int j = 0; j < 4; j++) {
            int row = ldrow + j * 32;
            int rg = row0 + row;
            pa[j] = (rg < Mtot)
                ? *(const float4*)(X + (size_t)rg * K + k0 + ldc4 * 4)
                : make_float4(0.f, 0.f, 0.f, 0.f);
            pb[j] = *(const float4*)(Wb + (size_t)(ldrow + j * 32) * K + k0 + ldc4 * 4);
        }
    };
    auto stage = [&]() {
#pragma unroll
        for (int j = 0; j < 4; j++) {
            int row = ldrow + j * 32;
            float4 va = pa[j], vb = pb[j];
            va.x = tf32_rn(va.x); va.y = tf32_rn(va.y);
            va.z = tf32_rn(va.z); va.w = tf32_rn(va.w);
            vb.x = tf32_rn(vb.x); vb.y = tf32_rn(vb.y);
            vb.z = tf32_rn(vb.z); vb.w = tf32_rn(vb.w);
            *(float4*)(As + row * LDA + ldc4 * 4) = va;
            *(float4*)(Bs + row * LDA + ldc4 * 4) = vb;
        }
    };

    float acc[2][8][4];
#pragma unroll
    for (int mt = 0; mt < 2; mt++)
#pragma unroll
        for (int nt = 0; nt < 8; nt++)
#pragma unroll
            for (int i = 0; i < 4; i++) acc[mt][nt][i] = 0.f;

    const int NC = K >> 5;
    prefetch(0);
    stage();
    __syncthreads();

    const int arow = wm * 32 + tr;
    const int brow = wn * 64 + tr;

    for (int c = 0; c < NC; c++) {
        if (c + 1 < NC) prefetch((c + 1) << 5);

#pragma unroll
        for (int ks = 0; ks < 4; ks++) {
            const int k = ks * 8 + tc;
            uint32_t af[2][4], bf[8][2];
#pragma unroll
            for (int mt = 0; mt < 2; mt++) {
                const float* p = As + (arow + mt * 16) * LDA + k;
                af[mt][0] = __float_as_uint(p[0]);
                af[mt][1] = __float_as_uint(p[8 * LDA]);
                af[mt][2] = __float_as_uint(p[4]);
                af[mt][3] = __float_as_uint(p[8 * LDA + 4]);
            }
#pragma unroll
            for (int nt = 0; nt < 8; nt++) {
                const float* p = Bs + (brow + nt * 8) * LDA + k;
                bf[nt][0] = __float_as_uint(p[0]);
                bf[nt][1] = __float_as_uint(p[4]);
            }
#pragma unroll
            for (int mt = 0; mt < 2; mt++)
#pragma unroll
                for (int nt = 0; nt < 8; nt++)
                    mma8(acc[mt][nt], af[mt], bf[nt]);
        }

        if (c + 1 < NC) {
            __syncthreads();
            stage();
            __syncthreads();
        }
    }

    if (S == 0) {
        const int cb = blockIdx.y * 128 + wn * 64;
#pragma unroll
        for (int mt = 0; mt < 2; mt++) {
            const int r0 = row0 + wm * 32 + mt * 16 + tr;
#pragma unroll
            for (int nt = 0; nt < 8; nt++) {
                const int c0 = cb + nt * 8 + 2 * tc;
                if (r0 < Mtot)
                    *(float2*)(Y + (size_t)r0 * ldy + c0) =
                        make_float2(acc[mt][nt][0], acc[mt][nt][1]);
                if (r0 + 8 < Mtot)
                    *(float2*)(Y + (size_t)(r0 + 8) * ldy + c0) =
                        make_float2(acc[mt][nt][2], acc[mt][nt][3]);
            }
        }
    } else {
        __syncthreads();   // staging buffers -> epilogue buffer reuse
#pragma unroll
        for (int mt = 0; mt < 2; mt++) {
            const int rr = wm * 32 + mt * 16 + tr;
            const float m0 = msk[rr], m1 = msk[rr + 8];
#pragma unroll
            for (int nt = 0; nt < 8; nt++) {
                const int cc = wn * 64 + nt * 8 + 2 * tc;
                buf[rr * EPI_STRIDE + cc]           = fmaxf(acc[mt][nt][0], 0.f) * m0;
                buf[rr * EPI_STRIDE + cc + 1]       = fmaxf(acc[mt][nt][1], 0.f) * m0;
                buf[(rr + 8) * EPI_STRIDE + cc]     = fmaxf(acc[mt][nt][2], 0.f) * m1;
                buf[(rr + 8) * EPI_STRIDE + cc + 1] = fmaxf(acc[mt][nt][3], 0.f) * m1;
            }
        }
        __syncthreads();
        const int G = Mtot / S;
        for (int tt = t; tt < GPC * 128; tt += THREADS) {
            const int g = tt >> 7, cc = tt & 127;
            const int og = blockIdx.x * GPC + g;
            if (og < G) {
                float m = 0.f;
#pragma unroll
                for (int r = 0; r < S; r++)
                    m = fmaxf(m, buf[(g * S + r) * EPI_STRIDE + cc]);
                Y[(size_t)og * 256 + blockIdx.y * 128 + cc] = m;
            }
        }
    }
}

// ---------------------------------------------------------------------------
// fp32 SIMT gemm for the final OUT projection (tiny; avoids a 3rd tf32 stage).
// ---------------------------------------------------------------------------
#define KC 32
__global__ __launch_bounds__(128) void gemm_f32(
    const float* __restrict__ X, int K,
    const float* __restrict__ W, int N,
    float* __restrict__ Y, int ldy)
{
    __shared__ float4 Wv[KC / 4][256];
    __shared__ float4 Xs[16][KC / 4];

    const int row0 = blockIdx.x * 16;
    const int t = threadIdx.x;
    float acc0[16];
#pragma unroll
    for (int r = 0; r < 16; r++) acc0[r] = 0.f;
    const int nload = N * (KC / 4);

    for (int k0 = 0; k0 < K; k0 += KC) {
        {
            int row = t >> 3, j = t & 7;
            Xs[row][j] = *reinterpret_cast<const float4*>(
                &X[(size_t)(row0 + row) * K + k0 + 4 * j]);
        }
        for (int idx = t; idx < nload; idx += 128) {
            int n = idx >> 3, j = idx & 7;
            Wv[j][n] = *reinterpret_cast<const float4*>(&W[(size_t)n * K + k0 + 4 * j]);
        }
        __syncthreads();
#pragma unroll
        for (int j = 0; j < KC / 4; j++) {
            float4 w0 = Wv[j][t];
#pragma unroll
            for (int r = 0; r < 16; r++) {
                float4 x = Xs[r][j];
                acc0[r] += x.x * w0.x + x.y * w0.y + x.z * w0.z + x.w * w0.w;
            }
        }
        __syncthreads();
    }
#pragma unroll
    for (int r = 0; r < 16; r++)
        Y[(size_t)(row0 + r) * ldy + t] = acc0[r];
}

// ---------------------------------------------------------------------------
// Host driver — 10 graph-capturable launches on the default stream.
// ---------------------------------------------------------------------------
extern "C" void kernel_launch(void* const* d_in, const int* in_sizes, int n_in,
                              void* d_out, int out_size)
{
    const float* h0    = (const float*)d_in[0];
    const float* h1    = (const float*)d_in[1];
    const float* h2    = (const float*)d_in[2];
    const float* mask0 = (const float*)d_in[3];
    const float* mask1 = (const float*)d_in[4];
    const float* Ws0   = (const float*)d_in[5];
    const float* Wn0   = (const float*)d_in[6];
    const float* Wp0   = (const float*)d_in[7];
    const float* Ws1   = (const float*)d_in[8];
    const float* Wn1   = (const float*)d_in[9];
    const float* Wp1   = (const float*)d_in[10];
    const float* Wout  = (const float*)d_in[11];
    float* out = (float*)d_out;

    float *pool1, *pool0, *state1, *state0, *pooled, *fin;
    cudaGetSymbolAddress((void**)&pool1,  g_pool1);
    cudaGetSymbolAddress((void**)&pool0,  g_pool0);
    cudaGetSymbolAddress((void**)&state1, g_state1);
    cudaGetSymbolAddress((void**)&state0, g_state0);
    cudaGetSymbolAddress((void**)&pooled, g_pooled);
    cudaGetSymbolAddress((void**)&fin,    g_fin);

    static int init_done = 0;
    if (!init_done) {
        cudaFuncSetAttribute(mma_kernel<25>, cudaFuncAttributeMaxDynamicSharedMemorySize, SMEM_DYN);
        cudaFuncSetAttribute(mma_kernel<10>, cudaFuncAttributeMaxDynamicSharedMemorySize, SMEM_DYN);
        cudaFuncSetAttribute(mma_kernel<0>,  cudaFuncAttributeMaxDynamicSharedMemorySize, SMEM_DYN);
        init_done = 1;
    }

    const int B = 1024;

    // ---- layer 0 ----
    // pool1 = maxpool_25 relu(h2 @ Wn0^T) * mask1      (B*10, 256)
    mma_kernel<25><<<dim3(2048, 2), THREADS, SMEM_DYN>>>(h2, Wn0, mask1, pool1, 256, B * 250, 0);
    // pool0 = maxpool_10 relu(h1 @ Wn0^T) * mask0      (B, 256)
    mma_kernel<10><<<dim3(86, 2),   THREADS, SMEM_DYN>>>(h1, Wn0, mask0, pool0, 256, B * 10, 0);

    // state1 = concat( h1 @ Ws0^T , pool1 @ Wp0^T )    (B*10, 512)
    mma_kernel<0><<<dim3(80, 2), THREADS, SMEM_DYN>>>(h1,    Ws0, nullptr, state1,       256, B * 10, 512);
    mma_kernel<0><<<dim3(80, 2), THREADS, SMEM_DYN>>>(pool1, Wp0, nullptr, state1 + 256, 256, B * 10, 512);

    // state0 = concat( h0 @ Ws0^T , pool0 @ Wp0^T )    (B, 512)
    mma_kernel<0><<<dim3(8, 2), THREADS, SMEM_DYN>>>(h0,    Ws0, nullptr, state0,       256, B, 512);
    mma_kernel<0><<<dim3(8, 2), THREADS, SMEM_DYN>>>(pool0, Wp0, nullptr, state0 + 256, 256, B, 512);

    // ---- layer 1 ----
    // pooled = maxpool_10 relu(state1 @ Wn1^T) * mask0 (B, 256), K=512
    mma_kernel<10><<<dim3(86, 2), THREADS, SMEM_DYN>>>(state1, Wn1, mask0, pooled, 512, B * 10, 0);

    // fin = concat( state0 @ Ws1^T , pooled @ Wp1^T )  (B, 512)
    mma_kernel<0><<<dim3(8, 2), THREADS, SMEM_DYN>>>(state0, Ws1, nullptr, fin,       512, B, 512);
    mma_kernel<0><<<dim3(8, 2), THREADS, SMEM_DYN>>>(pooled, Wp1, nullptr, fin + 256, 256, B, 512);

    // ---- output (fp32 SIMT) ----
    gemm_f32<<<B / 16, 128>>>(fin, 512, Wout, 128, out, 128);
}